// round 14
// baseline (speedup 1.0000x reference)
#include <cuda_runtime.h>
#include <cuda_fp16.h>
#include <cstdint>
#include <cstddef>

// ============================================================================
// Problem: B=8, Lq=Lk=2048, D=768
//   q = queries@Wq^T+bq ; v = values@Wv^T+bv ; k = v@Wk^T+bk
//   attn = sigmoid(mask ? q@k^T : -1e9) ; out = attn@v
//
// Plain sm_100 target. mma.sync.m16n8k16.f32.f16.f16.f32 + ldmatrix + cp.async.
// Pure fp16 single-plane everywhere (ISA-minimum 80.6G MACs; rel_err
// 8.06e-4 measured, arithmetic unchanged here).
// R14 vs R13 (614us): inner loop flattened to one 6-ldsm burst + one 16-mma
// burst per ks with fragments scoped at ks level, giving ptxas freedom to
// software-pipeline ks+1 ldsm under ks mma (tensor was stuck at ~50% with
// ldsm->mma serial bursts). BK=64 / 3-stage / 2 CTA/SM unchanged.
// ============================================================================

#define LQn 2048
#define LKn 2048
#define Dn  768
#define Bn  8
#define MR  (Bn * LQn)          // 16384

typedef __half fp16;

// ---------------- static device scratch (no cudaMalloc allowed) -------------
static __device__ fp16 g_qin[(size_t)MR * Dn];
static __device__ fp16 g_vin[(size_t)MR * Dn];
static __device__ fp16 g_wq[(size_t)Dn * Dn];
static __device__ fp16 g_wk[(size_t)Dn * Dn];
static __device__ fp16 g_wv[(size_t)Dn * Dn];
static __device__ fp16 g_q[(size_t)MR * Dn];
static __device__ fp16 g_k[(size_t)MR * Dn];
static __device__ fp16 g_v[(size_t)MR * Dn];
static __device__ fp16 g_at[(size_t)Bn * LQn * LKn];
static __device__ int  g_mask_mode;   // 0=byte, 1=int32, 2=float32

// ---------------- PTX helpers ------------------------------------------------
__device__ __forceinline__ uint32_t smem_u32(const void* p) {
    uint32_t a;
    asm("{ .reg .u64 t; cvta.to.shared.u64 t, %1; cvt.u32.u64 %0, t; }"
        : "=r"(a) : "l"(p));
    return a;
}

__device__ __forceinline__ void cpa16(uint32_t s, const void* g) {
    asm volatile("cp.async.cg.shared.global [%0], [%1], 16;"
                 :: "r"(s), "l"(g) : "memory");
}
#define CP_COMMIT() asm volatile("cp.async.commit_group;" ::: "memory")
#define CP_WAIT1()  asm volatile("cp.async.wait_group 1;"  ::: "memory")

__device__ __forceinline__ void ldsm4(uint32_t* r, uint32_t a) {
    asm volatile("ldmatrix.sync.aligned.m8n8.x4.shared.b16 {%0,%1,%2,%3}, [%4];"
                 : "=r"(r[0]), "=r"(r[1]), "=r"(r[2]), "=r"(r[3]) : "r"(a));
}
__device__ __forceinline__ void ldsm4t(uint32_t* r, uint32_t a) {
    asm volatile("ldmatrix.sync.aligned.m8n8.x4.trans.shared.b16 {%0,%1,%2,%3}, [%4];"
                 : "=r"(r[0]), "=r"(r[1]), "=r"(r[2]), "=r"(r[3]) : "r"(a));
}
__device__ __forceinline__ void mma16816(float* c, const uint32_t* a, const uint32_t* b) {
    asm volatile(
        "mma.sync.aligned.m16n8k16.row.col.f32.f16.f16.f32 "
        "{%0,%1,%2,%3}, {%4,%5,%6,%7}, {%8,%9}, {%0,%1,%2,%3};"
        : "+f"(c[0]), "+f"(c[1]), "+f"(c[2]), "+f"(c[3])
        : "r"(a[0]), "r"(a[1]), "r"(a[2]), "r"(a[3]), "r"(b[0]), "r"(b[1]));
}

__device__ __forceinline__ float sigf(float x) {
    return 1.0f / (1.0f + __expf(-x));
}

// ---------------- small kernels ----------------------------------------------
__global__ void detect_mask_kernel(const unsigned* __restrict__ w, int n) {
    int anyF = 0, anyO = 0;
    for (int i = threadIdx.x; i < n; i += blockDim.x) {
        unsigned x = w[i];
        anyF |= (x == 0x3F800000u);
        anyO |= (x != 0u && x != 1u && x != 0x3F800000u);
    }
    anyF = __syncthreads_or(anyF);
    anyO = __syncthreads_or(anyO);
    if (threadIdx.x == 0) g_mask_mode = anyF ? 2 : (anyO ? 0 : 1);
}

// Fused prep: convert all five fp32 inputs to single fp16 planes.
__global__ void prep_kernel(const float* __restrict__ queries,
                            const float* __restrict__ values,
                            const float* __restrict__ Wq,
                            const float* __restrict__ Wk,
                            const float* __restrict__ Wv) {
    const int N4 = MR * Dn / 4;          // 3,145,728
    const int W4 = Dn * Dn / 4;          // 147,456
    int i = blockIdx.x * blockDim.x + threadIdx.x;

    const float* src;
    fp16* dh;
    int j = i;
    if (j < N4)                 { src = queries; dh = g_qin; }
    else if ((j -= N4) < N4)    { src = values;  dh = g_vin; }
    else if ((j -= N4) < W4)    { src = Wq; dh = g_wq; }
    else if ((j -= W4) < W4)    { src = Wk; dh = g_wk; }
    else if ((j -= W4) < W4)    { src = Wv; dh = g_wv; }
    else return;

    float4 x = reinterpret_cast<const float4*>(src)[j];
    reinterpret_cast<__half2*>(dh)[j * 2 + 0] =
        __halves2half2(__float2half_rn(x.x), __float2half_rn(x.y));
    reinterpret_cast<__half2*>(dh)[j * 2 + 1] =
        __halves2half2(__float2half_rn(x.z), __float2half_rn(x.w));
}

// ---------------- GEMM body ---------------------------------------------------
// CTA tile 128x128, BK=64, 8 warps (warp tile 32x64), 3 stage buffers with
// 2 cp.async groups in flight, ONE __syncthreads per chunk, 2 CTAs/SM.
// Pure fp16 1-product: acc += A*B. Inner loop: per ks, 6 ldsm then 16 mma,
// fragments scoped at ks level (ptxas can pipeline ks+1 ldsm under ks mma).
// EPI: 1 = mask+sigmoid, store fp16 | 2 = plain fp32 store | 3 = +bias, fp16.
// Stage layout (32 KB): A@0  B@16K.  EPI1: mask tile @ 96K (16 KB).
// A / B-NT tile: 128 rows x 64 k fp16, 128 B/row:
//   addr = r*128 + ((c ^ (r&7)) << 4), c in 0..7
// B NN tile: 64 k x 128 n fp16, 256 B/row:
//   addr = k*256 + ((ns ^ (k&7)) << 4), ns in 0..15

template<int EPI, bool BTRANS>
__device__ __forceinline__ void
gemm_body(char* smem, uint32_t sm0,
          const fp16* __restrict__ Ap, const fp16* __restrict__ Bp,
          fp16* __restrict__ Oh, float* __restrict__ Of,
          const float* __restrict__ bias, const void* __restrict__ mask,
          int lda, int ldb, int ldo, int K,
          long sA, long sB, long sO,
          int z, int mbase, int nbase)
{
    constexpr uint32_t STAGE = 32768u;
    constexpr uint32_t MASKOFF = 3u * STAGE;     // 98304

    const int tid  = threadIdx.x;

    Ap += (size_t)z * sA;
    Bp += (size_t)z * sB;

    const int warp = tid >> 5;
    const int lane = tid & 31;
    const int wm = warp >> 1;          // 0..3 -> rows wm*32
    const int wn = warp & 1;           // 0..1 -> cols wn*64
    const int m8 = lane >> 3;
    const int l8 = lane & 7;

    const int C = K >> 6;              // chunks of 64
    const int mode = (EPI == 1) ? g_mask_mode : 0;

    auto issue = [&](int c) {
        const int s = c - (c / 3) * 3;
        const uint32_t sb = sm0 + (uint32_t)s * STAGE;
        const size_t ka = (size_t)c * 64;
        {
            const fp16* ga = Ap + (size_t)mbase * lda + ka;
#pragma unroll
            for (int i = 0; i < 4; ++i) {
                int seg = tid + i * 256;          // 0..1023
                int r = seg >> 3, cc = seg & 7;
                uint32_t sa = sb + r * 128 + ((cc ^ (r & 7)) << 4);
                cpa16(sa, ga + (size_t)r * lda + cc * 8);
            }
        }
        if (!BTRANS) {
            const fp16* gb = Bp + (size_t)nbase * ldb + ka;
#pragma unroll
            for (int i = 0; i < 4; ++i) {
                int seg = tid + i * 256;
                int r = seg >> 3, cc = seg & 7;
                uint32_t sa = sb + 16384 + r * 128 + ((cc ^ (r & 7)) << 4);
                cpa16(sa, gb + (size_t)r * ldb + cc * 8);
            }
        } else {
            const fp16* gb = Bp + ka * ldb + nbase;
#pragma unroll
            for (int i = 0; i < 4; ++i) {
                int seg = tid + i * 256;
                int k = seg >> 4, ns = seg & 15;
                uint32_t sa = sb + 16384 + k * 256 + ((ns ^ (k & 7)) << 4);
                cpa16(sa, gb + (size_t)k * ldb + ns * 8);
            }
        }
    };

    // EPI1 byte-mask: prefetch the CTA's 128x128-byte mask tile with group 0.
    if (EPI == 1 && mode == 0) {
        const unsigned char* mp = (const unsigned char*)mask
            + (size_t)z * ((size_t)LQn * LKn) + (size_t)mbase * LKn + nbase;
#pragma unroll
        for (int i = 0; i < 4; ++i) {
            int seg = tid + i * 256;              // 0..1023
            int r = seg >> 3, cc = seg & 7;       // 128 rows x 8 x16B
            cpa16(sm0 + MASKOFF + r * 128 + cc * 16,
                  mp + (size_t)r * LKn + cc * 16);
        }
    }
    issue(0); CP_COMMIT();
    issue(1); CP_COMMIT();

    float acc[2][8][4];
#pragma unroll
    for (int a = 0; a < 2; ++a)
#pragma unroll
        for (int b = 0; b < 8; ++b)
#pragma unroll
            for (int d = 0; d < 4; ++d) acc[a][b][d] = 0.0f;

    for (int c = 0; c < C; ++c) {
        CP_WAIT1();                 // stage c%3 resident (<=1 group pending)
        __syncthreads();            // all warps done with stage (c-1)%3

        // refill the stage drained LAST iteration: (c+2)%3 == (c-1)%3
        if (c + 2 < C) issue(c + 2);
        CP_COMMIT();

        const int s = c - (c / 3) * 3;
        const uint32_t sb = sm0 + (uint32_t)s * STAGE;

#pragma unroll
        for (int ks = 0; ks < 4; ++ks) {
            // ---- one ldsm burst: 2 A + 4 B (fragments scoped per-ks) ----
            uint32_t ahf[2][4];
            uint32_t bhf[4][4];
#pragma unroll
            for (int mt = 0; mt < 2; ++mt) {
                int r = wm * 32 + mt * 16 + (m8 & 1) * 8 + l8;
                int cA = 2 * ks + (m8 >> 1);
                uint32_t off = r * 128 + ((cA ^ (r & 7)) << 4);
                ldsm4(ahf[mt], sb + off);
            }
#pragma unroll
            for (int g = 0; g < 4; ++g) {
                if (!BTRANS) {
                    int n = wn * 64 + g * 16 + (m8 >> 1) * 8 + l8;
                    int cB = 2 * ks + (m8 & 1);
                    uint32_t off = n * 128 + ((cB ^ (n & 7)) << 4);
                    ldsm4(bhf[g], sb + 16384 + off);
                } else {
                    int k = ks * 16 + (m8 & 1) * 8 + l8;
                    int ns = ((wn * 64 + g * 16) >> 3) + (m8 >> 1);
                    uint32_t off = k * 256 + ((ns ^ (k & 7)) << 4);
                    ldsm4t(bhf[g], sb + 16384 + off);
                }
            }
            // ---- one mma burst: 16 (same per-acc order as before) ----
#pragma unroll
            for (int h2 = 0; h2 < 2; ++h2)
#pragma unroll
                for (int mt = 0; mt < 2; ++mt)
#pragma unroll
                    for (int ntl = 0; ntl < 4; ++ntl) {
                        const int nt = h2 * 4 + ntl;
                        mma16816(acc[mt][nt], ahf[mt],
                                 &bhf[nt >> 1][(nt & 1) * 2]);
                    }
        }
    }

    // ---------------- epilogue ------------------------------------------------
    const int rb = mbase + wm * 32 + (lane >> 2);
    const int cb = nbase + wn * 64 + (lane & 3) * 2;

    if (EPI == 1 || EPI == 3) { Oh += (size_t)z * sO; }
    if (EPI == 2) { Of += (size_t)z * sO; }

#pragma unroll
    for (int mt = 0; mt < 2; ++mt)
#pragma unroll
        for (int h = 0; h < 2; ++h) {
            const int gr = rb + mt * 16 + h * 8;
#pragma unroll
            for (int nt = 0; nt < 8; ++nt) {
                const int gc = cb + nt * 8;
                float x0 = acc[mt][nt][h * 2 + 0];
                float x1 = acc[mt][nt][h * 2 + 1];

                if (EPI == 3) {
                    x0 += bias[gc];
                    x1 += bias[gc + 1];
                } else if (EPI == 1) {
                    int f0, f1;
                    if (mode == 0) {
                        const unsigned char* ms = (const unsigned char*)smem
                            + MASKOFF + (size_t)(gr - mbase) * 128 + (gc - nbase);
                        f0 = ms[0]; f1 = ms[1];
                    } else {
                        const size_t mo = (size_t)z * ((size_t)LQn * LKn)
                                        + (size_t)gr * LKn + gc;
                        if (mode == 1) {
                            const int* mp = (const int*)mask + mo;
                            f0 = mp[0]; f1 = mp[1];
                        } else {
                            const float* mp = (const float*)mask + mo;
                            f0 = (mp[0] != 0.0f); f1 = (mp[1] != 0.0f);
                        }
                    }
                    x0 = f0 ? sigf(x0) : 0.0f;
                    x1 = f1 ? sigf(x1) : 0.0f;
                }

                if (EPI == 2) {
                    float2 p; p.x = x0; p.y = x1;
                    *reinterpret_cast<float2*>(Of + (size_t)gr * ldo + gc) = p;
                } else {
                    __half2 ph = __halves2half2(__float2half_rn(x0),
                                                __float2half_rn(x1));
                    *reinterpret_cast<__half2*>(Oh + (size_t)gr * ldo + gc) = ph;
                }
            }
        }
}

// ---------------- kernels -----------------------------------------------------
template<int EPI, bool BTRANS>
__global__ void __launch_bounds__(256, 2)
gemm_fp16(const fp16* __restrict__ Ap, const fp16* __restrict__ Bp,
          fp16* __restrict__ Oh, float* __restrict__ Of,
          const float* __restrict__ bias, const void* __restrict__ mask,
          int lda, int ldb, int ldo, int K,
          long sA, long sB, long sO)
{
    extern __shared__ char smem[];
    gemm_body<EPI, BTRANS>(smem, smem_u32(smem),
                           Ap, Bp, Oh, Of, bias, mask,
                           lda, ldb, ldo, K, sA, sB, sO,
                           blockIdx.z, blockIdx.y * 128, blockIdx.x * 128);
}

// Fused q-proj (z==0) + v-proj (z==1); both EPI3 (bias, fp16 store).
__global__ void __launch_bounds__(256, 2)
proj_dual(const fp16* __restrict__ qin, const fp16* __restrict__ wq,
          fp16* __restrict__ qo, const float* __restrict__ bq,
          const fp16* __restrict__ vin, const fp16* __restrict__ wv,
          fp16* __restrict__ vo, const float* __restrict__ bv)
{
    extern __shared__ char smem[];
    const uint32_t sm0 = smem_u32(smem);
    const int mb = blockIdx.y * 128, nb = blockIdx.x * 128;
    if (blockIdx.z == 0)
        gemm_body<3, false>(smem, sm0, qin, wq, qo, nullptr, bq, nullptr,
                            Dn, Dn, Dn, Dn, 0, 0, 0, 0, mb, nb);
    else
        gemm_body<3, false>(smem, sm0, vin, wv, vo, nullptr, bv, nullptr,
                            Dn, Dn, Dn, Dn, 0, 0, 0, 0, mb, nb);
}

// ---------------- host side ---------------------------------------------------
extern "C" void kernel_launch(void* const* d_in, const int* in_sizes, int n_in,
                              void* d_out, int out_size)
{
    const float* queries = (const float*)d_in[0];
    const float* values  = (const float*)d_in[1];
    const void*  mask    = d_in[2];
    const float* Wq = (const float*)d_in[3];
    const float* bq = (const float*)d_in[4];
    const float* Wk = (const float*)d_in[5];
    const float* bk = (const float*)d_in[6];
    const float* Wv = (const float*)d_in[7];
    const float* bv = (const float*)d_in[8];
    float* out = (float*)d_out;

    fp16 *q, *k, *v, *at, *qin, *vin, *wq, *wk, *wv;
    cudaGetSymbolAddress((void**)&qin, g_qin);
    cudaGetSymbolAddress((void**)&vin, g_vin);
    cudaGetSymbolAddress((void**)&wq,  g_wq);
    cudaGetSymbolAddress((void**)&wk,  g_wk);
    cudaGetSymbolAddress((void**)&wv,  g_wv);
    cudaGetSymbolAddress((void**)&q,   g_q);
    cudaGetSymbolAddress((void**)&k,   g_k);
    cudaGetSymbolAddress((void**)&v,   g_v);
    cudaGetSymbolAddress((void**)&at,  g_at);

    constexpr int SMEM   = 3 * 32768;            // 96 KB
    constexpr int SMEM_M = 3 * 32768 + 16384;    // 112 KB (score: +mask tile)
    static int attr_done = 0;
    if (!attr_done) {
        cudaFuncSetAttribute(proj_dual,
                             cudaFuncAttributeMaxDynamicSharedMemorySize, SMEM);
        cudaFuncSetAttribute(gemm_fp16<3, false>,
                             cudaFuncAttributeMaxDynamicSharedMemorySize, SMEM);
        cudaFuncSetAttribute(gemm_fp16<1, false>,
                             cudaFuncAttributeMaxDynamicSharedMemorySize, SMEM_M);
        cudaFuncSetAttribute(gemm_fp16<2, true>,
                             cudaFuncAttributeMaxDynamicSharedMemorySize, SMEM);
        attr_done = 1;
    }

    // launch 1: mask dtype detection
    detect_mask_kernel<<<1, 256>>>((const unsigned*)mask, 8192);

    // launch 2: fused prep (pure fp16 converts)
    {
        const int N4 = MR * Dn / 4, W4 = Dn * Dn / 4;
        const int total = 2 * N4 + 3 * W4;
        prep_kernel<<<(total + 255) / 256, 256>>>(queries, values, Wq, Wk, Wv);
    }

    // launch 3: fused q-proj + v-proj
    proj_dual<<<dim3(6, 128, 2), 256, SMEM>>>(
        qin, wq, q, bq, vin, wv, v, bv);

    // launch 4: k = v @ Wk^T + bk
    gemm_fp16<3, false><<<dim3(6, 128, 1), 256, SMEM>>>(
        v, wk, k, nullptr, bk, nullptr,
        Dn, Dn, Dn, Dn, 0, 0, 0);

    // launch 5: score = sigmoid(mask ? q@k^T : -1e9), mask tile in smem
    gemm_fp16<1, false><<<dim3(16, 16, Bn), 256, SMEM_M>>>(
        q, k, at, nullptr, nullptr, mask,
        Dn, Dn, LKn, Dn,
        (long)LQn * Dn, (long)LKn * Dn, (long)LQn * LKn);

    // launch 6: out = attn @ v (NN)
    gemm_fp16<2, true><<<dim3(6, 16, Bn), 256, SMEM>>>(
        at, v, nullptr, out, nullptr, nullptr,
        LKn, Dn, Dn, LKn,
        (long)LQn * LKn, (long)LKn * Dn, (long)LQn * Dn);
}

// round 15
// speedup vs baseline: 1.0312x; 1.0312x over previous
#include <cuda_runtime.h>
#include <cuda_fp16.h>
#include <cstdint>
#include <cstddef>

// ============================================================================
// Problem: B=8, Lq=Lk=2048, D=768
//   q = queries@Wq^T+bq ; v = values@Wv^T+bv ; k = v@Wk^T+bk
//   attn = sigmoid(mask ? q@k^T : -1e9) ; out = attn@v
//
// Plain sm_100 target. mma.sync.m16n8k16.f32.f16.f16.f32 + ldmatrix + cp.async.
// Pure fp16 single-plane everywhere (ISA-minimum 80.6G MACs; rel_err
// 8.062989e-4, arithmetic order unchanged here -> bit-identical).
// R15 vs R14 (620.9us, neutral): latency-bound diagnosis (tensor~50%,
// L1~50%, issue 26%, nothing saturated). Same per-warp program, finer
// concurrency: 128-thread CTAs (4 warps, tile 64x128), BK=32, 3-stage
// (12 KB/stage), 4 CTAs/SM (regs 128*128*4 = full RF). Four independent
// CTA pipelines per SM absorb barrier/fill phases; 4-warp barriers.
// Mask smem prefetch dropped (was worth ~7us; doesn't fit smem budget).
// ============================================================================

#define LQn 2048
#define LKn 2048
#define Dn  768
#define Bn  8
#define MR  (Bn * LQn)          // 16384

typedef __half fp16;

// ---------------- static device scratch (no cudaMalloc allowed) -------------
static __device__ fp16 g_qin[(size_t)MR * Dn];
static __device__ fp16 g_vin[(size_t)MR * Dn];
static __device__ fp16 g_wq[(size_t)Dn * Dn];
static __device__ fp16 g_wk[(size_t)Dn * Dn];
static __device__ fp16 g_wv[(size_t)Dn * Dn];
static __device__ fp16 g_q[(size_t)MR * Dn];
static __device__ fp16 g_k[(size_t)MR * Dn];
static __device__ fp16 g_v[(size_t)MR * Dn];
static __device__ fp16 g_at[(size_t)Bn * LQn * LKn];
static __device__ int  g_mask_mode;   // 0=byte, 1=int32, 2=float32

// ---------------- PTX helpers ------------------------------------------------
__device__ __forceinline__ uint32_t smem_u32(const void* p) {
    uint32_t a;
    asm("{ .reg .u64 t; cvta.to.shared.u64 t, %1; cvt.u32.u64 %0, t; }"
        : "=r"(a) : "l"(p));
    return a;
}

__device__ __forceinline__ void cpa16(uint32_t s, const void* g) {
    asm volatile("cp.async.cg.shared.global [%0], [%1], 16;"
                 :: "r"(s), "l"(g) : "memory");
}
#define CP_COMMIT() asm volatile("cp.async.commit_group;" ::: "memory")
#define CP_WAIT1()  asm volatile("cp.async.wait_group 1;"  ::: "memory")

__device__ __forceinline__ void ldsm4(uint32_t* r, uint32_t a) {
    asm volatile("ldmatrix.sync.aligned.m8n8.x4.shared.b16 {%0,%1,%2,%3}, [%4];"
                 : "=r"(r[0]), "=r"(r[1]), "=r"(r[2]), "=r"(r[3]) : "r"(a));
}
__device__ __forceinline__ void ldsm4t(uint32_t* r, uint32_t a) {
    asm volatile("ldmatrix.sync.aligned.m8n8.x4.trans.shared.b16 {%0,%1,%2,%3}, [%4];"
                 : "=r"(r[0]), "=r"(r[1]), "=r"(r[2]), "=r"(r[3]) : "r"(a));
}
__device__ __forceinline__ void mma16816(float* c, const uint32_t* a, const uint32_t* b) {
    asm volatile(
        "mma.sync.aligned.m16n8k16.row.col.f32.f16.f16.f32 "
        "{%0,%1,%2,%3}, {%4,%5,%6,%7}, {%8,%9}, {%0,%1,%2,%3};"
        : "+f"(c[0]), "+f"(c[1]), "+f"(c[2]), "+f"(c[3])
        : "r"(a[0]), "r"(a[1]), "r"(a[2]), "r"(a[3]), "r"(b[0]), "r"(b[1]));
}

__device__ __forceinline__ float sigf(float x) {
    return 1.0f / (1.0f + __expf(-x));
}

// ---------------- small kernels ----------------------------------------------
__global__ void detect_mask_kernel(const unsigned* __restrict__ w, int n) {
    int anyF = 0, anyO = 0;
    for (int i = threadIdx.x; i < n; i += blockDim.x) {
        unsigned x = w[i];
        anyF |= (x == 0x3F800000u);
        anyO |= (x != 0u && x != 1u && x != 0x3F800000u);
    }
    anyF = __syncthreads_or(anyF);
    anyO = __syncthreads_or(anyO);
    if (threadIdx.x == 0) g_mask_mode = anyF ? 2 : (anyO ? 0 : 1);
}

// Fused prep: convert all five fp32 inputs to single fp16 planes.
__global__ void prep_kernel(const float* __restrict__ queries,
                            const float* __restrict__ values,
                            const float* __restrict__ Wq,
                            const float* __restrict__ Wk,
                            const float* __restrict__ Wv) {
    const int N4 = MR * Dn / 4;          // 3,145,728
    const int W4 = Dn * Dn / 4;          // 147,456
    int i = blockIdx.x * blockDim.x + threadIdx.x;

    const float* src;
    fp16* dh;
    int j = i;
    if (j < N4)                 { src = queries; dh = g_qin; }
    else if ((j -= N4) < N4)    { src = values;  dh = g_vin; }
    else if ((j -= N4) < W4)    { src = Wq; dh = g_wq; }
    else if ((j -= W4) < W4)    { src = Wk; dh = g_wk; }
    else if ((j -= W4) < W4)    { src = Wv; dh = g_wv; }
    else return;

    float4 x = reinterpret_cast<const float4*>(src)[j];
    reinterpret_cast<__half2*>(dh)[j * 2 + 0] =
        __halves2half2(__float2half_rn(x.x), __float2half_rn(x.y));
    reinterpret_cast<__half2*>(dh)[j * 2 + 1] =
        __halves2half2(__float2half_rn(x.z), __float2half_rn(x.w));
}

// ---------------- GEMM body ---------------------------------------------------
// CTA tile 64x128, BK=32, 4 warps (warp tile 32x64), 3 stage buffers with
// 2 cp.async groups in flight, ONE __syncthreads per chunk, 4 CTAs/SM.
// Pure fp16 1-product: acc += A*B.
// EPI: 1 = mask+sigmoid, store fp16 | 2 = plain fp32 store | 3 = +bias, fp16.
// Stage layout (12 KB): A@0 (4 KB)  B@4K (8 KB).
// A tile: 64 rows x 32 k fp16, 64 B/row: addr = r*64 + ((c ^ ((r>>1)&3)) << 4)
// B NT tile: 128 n x 32 k fp16, 64 B/row: same formula, n as row
// B NN tile: 32 k x 128 n fp16, 256 B/row: addr = k*256 + ((ns ^ (k&7)) << 4)

template<int EPI, bool BTRANS>
__device__ __forceinline__ void
gemm_body(char* smem, uint32_t sm0,
          const fp16* __restrict__ Ap, const fp16* __restrict__ Bp,
          fp16* __restrict__ Oh, float* __restrict__ Of,
          const float* __restrict__ bias, const void* __restrict__ mask,
          int lda, int ldb, int ldo, int K,
          long sA, long sB, long sO,
          int z, int mbase, int nbase)
{
    constexpr uint32_t STAGE = 12288u;

    const int tid  = threadIdx.x;

    Ap += (size_t)z * sA;
    Bp += (size_t)z * sB;

    const int warp = tid >> 5;         // 0..3
    const int lane = tid & 31;
    const int wm = warp >> 1;          // 0..1 -> rows wm*32
    const int wn = warp & 1;           // 0..1 -> cols wn*64
    const int m8 = lane >> 3;
    const int l8 = lane & 7;

    const int C = K >> 5;              // chunks of 32
    const int mode = (EPI == 1) ? g_mask_mode : 0;

    auto issue = [&](int c) {
        const int s = c - (c / 3) * 3;
        const uint32_t sb = sm0 + (uint32_t)s * STAGE;
        const size_t ka = (size_t)c * 32;
        {
            // A tile: 64 rows x 4 segs of 16B = 256 segs; 128 threads x 2
            const fp16* ga = Ap + (size_t)mbase * lda + ka;
#pragma unroll
            for (int i = 0; i < 2; ++i) {
                int seg = tid + i * 128;          // 0..255
                int r = seg >> 2, cc = seg & 3;
                uint32_t sa = sb + r * 64 + ((cc ^ ((r >> 1) & 3)) << 4);
                cpa16(sa, ga + (size_t)r * lda + cc * 8);
            }
        }
        if (!BTRANS) {
            // B NT: 128 rows x 4 segs = 512 segs; 128 threads x 4
            const fp16* gb = Bp + (size_t)nbase * ldb + ka;
#pragma unroll
            for (int i = 0; i < 4; ++i) {
                int seg = tid + i * 128;
                int r = seg >> 2, cc = seg & 3;
                uint32_t sa = sb + 4096 + r * 64 + ((cc ^ ((r >> 1) & 3)) << 4);
                cpa16(sa, gb + (size_t)r * ldb + cc * 8);
            }
        } else {
            // B NN: 32 k x 16 segs = 512 segs; 128 threads x 4
            const fp16* gb = Bp + ka * ldb + nbase;
#pragma unroll
            for (int i = 0; i < 4; ++i) {
                int seg = tid + i * 128;
                int k = seg >> 4, ns = seg & 15;
                uint32_t sa = sb + 4096 + k * 256 + ((ns ^ (k & 7)) << 4);
                cpa16(sa, gb + (size_t)k * ldb + ns * 8);
            }
        }
    };

    issue(0); CP_COMMIT();
    issue(1); CP_COMMIT();

    float acc[2][8][4];
#pragma unroll
    for (int a = 0; a < 2; ++a)
#pragma unroll
        for (int b = 0; b < 8; ++b)
#pragma unroll
            for (int d = 0; d < 4; ++d) acc[a][b][d] = 0.0f;

    for (int c = 0; c < C; ++c) {
        CP_WAIT1();                 // stage c%3 resident (<=1 group pending)
        __syncthreads();            // all warps done with stage (c-1)%3

        // refill the stage drained LAST iteration: (c+2)%3 == (c-1)%3
        if (c + 2 < C) issue(c + 2);
        CP_COMMIT();

        const int s = c - (c / 3) * 3;
        const uint32_t sb = sm0 + (uint32_t)s * STAGE;

#pragma unroll
        for (int ks = 0; ks < 2; ++ks) {
            uint32_t ahf[2][4];
#pragma unroll
            for (int mt = 0; mt < 2; ++mt) {
                int r = wm * 32 + mt * 16 + (m8 & 1) * 8 + l8;
                int cA = 2 * ks + (m8 >> 1);
                uint32_t off = r * 64 + ((cA ^ ((r >> 1) & 3)) << 4);
                ldsm4(ahf[mt], sb + off);
            }
#pragma unroll
            for (int h2 = 0; h2 < 2; ++h2) {
                uint32_t bhf[2][4];
#pragma unroll
                for (int gl = 0; gl < 2; ++gl) {
                    int g = h2 * 2 + gl;
                    if (!BTRANS) {
                        int n = wn * 64 + g * 16 + (m8 >> 1) * 8 + l8;
                        int cB = 2 * ks + (m8 & 1);
                        uint32_t off = n * 64 + ((cB ^ ((n >> 1) & 3)) << 4);
                        ldsm4(bhf[gl], sb + 4096 + off);
                    } else {
                        int k = ks * 16 + (m8 & 1) * 8 + l8;
                        int ns = ((wn * 64 + g * 16) >> 3) + (m8 >> 1);
                        uint32_t off = k * 256 + ((ns ^ (k & 7)) << 4);
                        ldsm4t(bhf[gl], sb + 4096 + off);
                    }
                }
#pragma unroll
                for (int mt = 0; mt < 2; ++mt)
#pragma unroll
                    for (int ntl = 0; ntl < 4; ++ntl)
                        mma16816(acc[mt][h2 * 4 + ntl], ahf[mt],
                                 &bhf[ntl >> 1][(ntl & 1) * 2]);
            }
        }
    }

    // ---------------- epilogue ------------------------------------------------
    const int rb = mbase + wm * 32 + (lane >> 2);
    const int cb = nbase + wn * 64 + (lane & 3) * 2;

    if (EPI == 1 || EPI == 3) { Oh += (size_t)z * sO; }
    if (EPI == 2) { Of += (size_t)z * sO; }

#pragma unroll
    for (int mt = 0; mt < 2; ++mt)
#pragma unroll
        for (int h = 0; h < 2; ++h) {
            const int gr = rb + mt * 16 + h * 8;
#pragma unroll
            for (int nt = 0; nt < 8; ++nt) {
                const int gc = cb + nt * 8;
                float x0 = acc[mt][nt][h * 2 + 0];
                float x1 = acc[mt][nt][h * 2 + 1];

                if (EPI == 3) {
                    x0 += bias[gc];
                    x1 += bias[gc + 1];
                } else if (EPI == 1) {
                    int f0, f1;
                    const size_t mo = (size_t)z * ((size_t)LQn * LKn)
                                    + (size_t)gr * LKn + gc;
                    if (mode == 0) {
                        const unsigned char* mp = (const unsigned char*)mask + mo;
                        f0 = mp[0]; f1 = mp[1];
                    } else if (mode == 1) {
                        const int* mp = (const int*)mask + mo;
                        f0 = mp[0]; f1 = mp[1];
                    } else {
                        const float* mp = (const float*)mask + mo;
                        f0 = (mp[0] != 0.0f); f1 = (mp[1] != 0.0f);
                    }
                    x0 = f0 ? sigf(x0) : 0.0f;
                    x1 = f1 ? sigf(x1) : 0.0f;
                }

                if (EPI == 2) {
                    float2 p; p.x = x0; p.y = x1;
                    *reinterpret_cast<float2*>(Of + (size_t)gr * ldo + gc) = p;
                } else {
                    __half2 ph = __halves2half2(__float2half_rn(x0),
                                                __float2half_rn(x1));
                    *reinterpret_cast<__half2*>(Oh + (size_t)gr * ldo + gc) = ph;
                }
            }
        }
}

// ---------------- kernels -----------------------------------------------------
template<int EPI, bool BTRANS>
__global__ void __launch_bounds__(128, 4)
gemm_fp16(const fp16* __restrict__ Ap, const fp16* __restrict__ Bp,
          fp16* __restrict__ Oh, float* __restrict__ Of,
          const float* __restrict__ bias, const void* __restrict__ mask,
          int lda, int ldb, int ldo, int K,
          long sA, long sB, long sO)
{
    extern __shared__ char smem[];
    gemm_body<EPI, BTRANS>(smem, smem_u32(smem),
                           Ap, Bp, Oh, Of, bias, mask,
                           lda, ldb, ldo, K, sA, sB, sO,
                           blockIdx.z, blockIdx.y * 64, blockIdx.x * 128);
}

// Fused q-proj (z==0) + v-proj (z==1); both EPI3 (bias, fp16 store).
__global__ void __launch_bounds__(128, 4)
proj_dual(const fp16* __restrict__ qin, const fp16* __restrict__ wq,
          fp16* __restrict__ qo, const float* __restrict__ bq,
          const fp16* __restrict__ vin, const fp16* __restrict__ wv,
          fp16* __restrict__ vo, const float* __restrict__ bv)
{
    extern __shared__ char smem[];
    const uint32_t sm0 = smem_u32(smem);
    const int mb = blockIdx.y * 64, nb = blockIdx.x * 128;
    if (blockIdx.z == 0)
        gemm_body<3, false>(smem, sm0, qin, wq, qo, nullptr, bq, nullptr,
                            Dn, Dn, Dn, Dn, 0, 0, 0, 0, mb, nb);
    else
        gemm_body<3, false>(smem, sm0, vin, wv, vo, nullptr, bv, nullptr,
                            Dn, Dn, Dn, Dn, 0, 0, 0, 0, mb, nb);
}

// ---------------- host side ---------------------------------------------------
extern "C" void kernel_launch(void* const* d_in, const int* in_sizes, int n_in,
                              void* d_out, int out_size)
{
    const float* queries = (const float*)d_in[0];
    const float* values  = (const float*)d_in[1];
    const void*  mask    = d_in[2];
    const float* Wq = (const float*)d_in[3];
    const float* bq = (const float*)d_in[4];
    const float* Wk = (const float*)d_in[5];
    const float* bk = (const float*)d_in[6];
    const float* Wv = (const float*)d_in[7];
    const float* bv = (const float*)d_in[8];
    float* out = (float*)d_out;

    fp16 *q, *k, *v, *at, *qin, *vin, *wq, *wk, *wv;
    cudaGetSymbolAddress((void**)&qin, g_qin);
    cudaGetSymbolAddress((void**)&vin, g_vin);
    cudaGetSymbolAddress((void**)&wq,  g_wq);
    cudaGetSymbolAddress((void**)&wk,  g_wk);
    cudaGetSymbolAddress((void**)&wv,  g_wv);
    cudaGetSymbolAddress((void**)&q,   g_q);
    cudaGetSymbolAddress((void**)&k,   g_k);
    cudaGetSymbolAddress((void**)&v,   g_v);
    cudaGetSymbolAddress((void**)&at,  g_at);

    constexpr int SMEM = 3 * 12288;              // 36 KB
    static int attr_done = 0;
    if (!attr_done) {
        cudaFuncSetAttribute(proj_dual,
                             cudaFuncAttributeMaxDynamicSharedMemorySize, SMEM);
        cudaFuncSetAttribute(gemm_fp16<3, false>,
                             cudaFuncAttributeMaxDynamicSharedMemorySize, SMEM);
        cudaFuncSetAttribute(gemm_fp16<1, false>,
                             cudaFuncAttributeMaxDynamicSharedMemorySize, SMEM);
        cudaFuncSetAttribute(gemm_fp16<2, true>,
                             cudaFuncAttributeMaxDynamicSharedMemorySize, SMEM);
        attr_done = 1;
    }

    // launch 1: mask dtype detection
    detect_mask_kernel<<<1, 256>>>((const unsigned*)mask, 8192);

    // launch 2: fused prep (pure fp16 converts)
    {
        const int N4 = MR * Dn / 4, W4 = Dn * Dn / 4;
        const int total = 2 * N4 + 3 * W4;
        prep_kernel<<<(total + 255) / 256, 256>>>(queries, values, Wq, Wk, Wv);
    }

    // launch 3: fused q-proj + v-proj (M tiles of 64)
    proj_dual<<<dim3(6, 256, 2), 128, SMEM>>>(
        qin, wq, q, bq, vin, wv, v, bv);

    // launch 4: k = v @ Wk^T + bk
    gemm_fp16<3, false><<<dim3(6, 256, 1), 128, SMEM>>>(
        v, wk, k, nullptr, bk, nullptr,
        Dn, Dn, Dn, Dn, 0, 0, 0);

    // launch 5: score = sigmoid(mask ? q@k^T : -1e9)
    gemm_fp16<1, false><<<dim3(16, 32, Bn), 128, SMEM>>>(
        q, k, at, nullptr, nullptr, mask,
        Dn, Dn, LKn, Dn,
        (long)LQn * Dn, (long)LKn * Dn, (long)LQn * LKn);

    // launch 6: out = attn @ v (NN)
    gemm_fp16<2, true><<<dim3(6, 32, Bn), 128, SMEM>>>(
        at, v, nullptr, out, nullptr, nullptr,
        LKn, Dn, Dn, LKn,
        (long)LQn * LKn, (long)LKn * Dn, (long)LQn * Dn);
}